// round 14
// baseline (speedup 1.0000x reference)
#include <cuda_runtime.h>
#include <cuda.h>
#include <cstdint>

// ---------------- problem constants (fixed for this dataset) ----------------
#define T_   8192
#define K_   2048
#define N_   4096
#define E_   8

#define BM       128         // M rows per CTA; cg2 pair covers 256
#define BN       512         // N per cg2 tile (2 x N=256 MMAs sharing one A stage)
#define MMA_N    256         // tcgen05 max N per instruction
#define BK       32          // 32 fp32 = 128B = one SW128 atom row
#define STAGES   4           // 48KB/stage/CTA -> 197KB smem (OCC=1)
#define KCHUNKS  (K_ / BK)   // 64
#define NT       (N_ / BN)   // 8
#define NTHREADS 192         // warps 0-3 epilogue, warp 4 MMA (leader), warp 5 TMA
#define CLUSTER  2
#define OCC      1
#define WSLOTS   4           // work-ring depth (dynamic tile scheduler)

// Arch-feature gate: tcgen05/TMEM asm may only appear in PTX whose .target is
// sm_103a/sm_100a (or family). The harness also builds a plain compute_103 PTX
// stage, which must get a tcgen05-free body or ptxas aborts.
#if defined(__CUDA_ARCH_FEAT_SM103_ALL) || defined(__CUDA_ARCH_FEAT_SM100_ALL) || \
    (defined(__CUDA_ARCH_SPECIFIC__) && (__CUDA_ARCH_SPECIFIC__ >= 1000)) || \
    (defined(__CUDA_ARCH_FAMILY_SPECIFIC__) && (__CUDA_ARCH_FAMILY_SPECIFIC__ >= 1000))
#define GG_HAS_TCGEN05 1
#else
#define GG_HAS_TCGEN05 0
#endif

// global ticket for dynamic tile scheduling (reset by gg_init each launch)
__device__ int g_ticket;

// ---------------- SMEM layout ----------------
#define SM_TMEM    0
#define SM_FULL    64                      // 4 mbarriers (stage full; leader's used by MMA)
#define SM_MMAD    128                     // 4 mbarriers (stage consumed; cg2 multicast commit)
#define SM_TILED0  192                     // 1 mbarrier  (half0 accumulated; cg2 multicast commit)
#define SM_TILED1  200                     // 1 mbarrier  (half1 accumulated; cg2 multicast commit)
#define SM_BUFF0   208                     // 1 mbarrier  (N-half0 accumulator freed; 8 -> leader)
#define SM_BUFF1   216                     // 1 mbarrier  (N-half1 accumulator freed; 8 -> leader)
#define SM_WORKV   256                     // 4 mbarriers (work slot valid)
#define SM_WORKF   320                     // 4 mbarriers (work slot free; count=10, leader only)
#define SM_RING    384                     // 4 ints (tile ids; -1 = sentinel)
#define SM_STAGE0  1024
#define A_BYTES    (BM * 128)              // 16384
#define B_BYTES    (2 * 128 * 128)         // 32768: two 128-row sub-panels per CTA
#define B_SUB      16384                   // offset of N-half-1 sub-panel within B
#define STAGE_BYTES (A_BYTES + B_BYTES)    // 49152 per CTA
#define STAGE_TX    (2 * STAGE_BYTES)      // 98304: both CTAs complete into leader's FULL
#define A_OFF(s)   (SM_STAGE0 + (s) * STAGE_BYTES)
#define B_OFF(s)   (A_OFF(s) + A_BYTES)
#define SMEM_TOTAL (SM_STAGE0 + STAGES * STAGE_BYTES)   // 197632 < 227KB

#define TMEM_COLS  512       // 256x512 fp32 accumulator (half0: cols 0-255, half1: 256-511)

// free-barrier arrival count: leader MMA (1) + 4 epi warps x 2 CTAs (8) + rank1 TMA (1)
#define WFREE_COUNT 10

// idesc: d=F32(1), a=TF32(2), b=TF32(2), N(=256)>>3 @17, M(=256)>>4 @24
static constexpr uint32_t IDESC =
    (1u << 4) | (2u << 7) | (2u << 10) | ((MMA_N / 8) << 17) | ((256 / 16) << 24);

// SW128 K-major smem descriptor base (Blackwell v1, LBO=1, SBO=64)
static constexpr uint64_t SMEM_DESC_BASE_SW128 =
    (uint64_t(2) << 61) | (uint64_t(1) << 46) | (uint64_t(64) << 32) | (uint64_t(1) << 16);
#define MAKE_SMEM_DESC(base_addr) \
    (SMEM_DESC_BASE_SW128 | ((uint64_t)((base_addr) >> 4) & 0x3FFF))

// ---------------- PTX helpers ----------------
__device__ __forceinline__ uint32_t smem_to_u32(const void* p) {
    uint32_t a;
    asm("{ .reg .u64 t; cvta.to.shared.u64 t, %1; cvt.u32.u64 %0, t; }" : "=r"(a) : "l"(p));
    return a;
}

#define MBARRIER_INIT(mbar, count) \
    asm volatile("mbarrier.init.shared.b64 [%0], %1;" :: "r"((uint32_t)(mbar)), "r"((uint32_t)(count)) : "memory")

#define MBARRIER_EXPECT_TX(mbar, tx) \
    asm volatile("mbarrier.arrive.expect_tx.shared.b64 _, [%0], %1;" :: "r"((uint32_t)(mbar)), "r"((uint32_t)(tx)) : "memory")

#define MBARRIER_ARRIVE(mbar) \
    asm volatile("mbarrier.arrive.shared.b64 _, [%0];" :: "r"((uint32_t)(mbar)) : "memory")

// Arrive on the leader CTA's (cluster rank 0) mbarrier at the same SMEM offset.
#define MBARRIER_ARRIVE_RANK0(mbar) \
    asm volatile("{\n\t.reg .b32 ra;\n\t" \
                 "mapa.shared::cluster.u32 ra, %0, 0;\n\t" \
                 "mbarrier.arrive.shared::cluster.b64 _, [ra];\n\t}" \
                 :: "r"((uint32_t)(mbar)) : "memory")

// Publish a tile id into BOTH CTAs' ring slot and arrive on both valid barriers.
// Cluster-scope release so the peer's acquire-wait sees the store.
#define RING_PUBLISH(ring_addr, validbar, val) \
    asm volatile("{\n\t.reg .b32 ra, rb;\n\t" \
                 "st.shared.b32 [%0], %2;\n\t" \
                 "mapa.shared::cluster.u32 ra, %0, 1;\n\t" \
                 "st.shared::cluster.b32 [ra], %2;\n\t" \
                 "mbarrier.arrive.release.cta.shared::cta.b64 _, [%1];\n\t" \
                 "mapa.shared::cluster.u32 rb, %1, 1;\n\t" \
                 "mbarrier.arrive.release.cluster.shared::cluster.b64 _, [rb];\n\t}" \
                 :: "r"((uint32_t)(ring_addr)), "r"((uint32_t)(validbar)), "r"((int)(val)) : "memory")

#define MBARRIER_WAIT_PARITY(mbar, parity) do {                                   \
    uint32_t _m = (uint32_t)(mbar); uint32_t _p = (uint32_t)(parity);             \
    asm volatile(                                                                 \
        "{\n\t.reg .pred P1;\n\t"                                                 \
        "WL_%=:\n\t"                                                              \
        "mbarrier.try_wait.parity.acquire.cta.shared::cta.b64 P1, [%0], %1, 0x989680;\n\t" \
        "@P1 bra.uni WD_%=;\n\t"                                                  \
        "bra.uni WL_%=;\n\t"                                                      \
        "WD_%=:\n\t}"                                                             \
        :: "r"(_m), "r"(_p) : "memory");                                          \
} while (0)

// acquire at CLUSTER scope: consumer of ring values written by the peer CTA
#define MBARRIER_WAIT_PARITY_ACQC(mbar, parity) do {                              \
    uint32_t _m = (uint32_t)(mbar); uint32_t _p = (uint32_t)(parity);             \
    asm volatile(                                                                 \
        "{\n\t.reg .pred P1;\n\t"                                                 \
        "WL_%=:\n\t"                                                              \
        "mbarrier.try_wait.parity.acquire.cluster.shared::cta.b64 P1, [%0], %1, 0x989680;\n\t" \
        "@P1 bra.uni WD_%=;\n\t"                                                  \
        "bra.uni WL_%=;\n\t"                                                      \
        "WD_%=:\n\t}"                                                             \
        :: "r"(_m), "r"(_p) : "memory");                                          \
} while (0)

#define MBARRIER_WAIT_PARITY_RELAXED(mbar, parity) do {                           \
    uint32_t _m = (uint32_t)(mbar); uint32_t _p = (uint32_t)(parity);             \
    asm volatile(                                                                 \
        "{\n\t.reg .pred P1;\n\t"                                                 \
        "WL_%=:\n\t"                                                              \
        "mbarrier.try_wait.parity.relaxed.cta.shared::cta.b64 P1, [%0], %1, 0x989680;\n\t" \
        "@P1 bra.uni WD_%=;\n\t"                                                  \
        "bra.uni WL_%=;\n\t"                                                      \
        "WD_%=:\n\t}"                                                             \
        :: "r"(_m), "r"(_p) : "memory");                                          \
} while (0)

#define CLUSTER_SYNC() do { \
    asm volatile("barrier.cluster.arrive.aligned;" ::: "memory"); \
    asm volatile("barrier.cluster.wait.aligned;" ::: "memory"); \
} while (0)

#if GG_HAS_TCGEN05

#define TCGEN05_ALLOC_CG2(smem_result, nCols) \
    asm volatile("tcgen05.alloc.cta_group::2.sync.aligned.shared::cta.b32 [%0], %1;" \
                 :: "r"((uint32_t)(smem_result)), "r"((uint32_t)(nCols)) : "memory")
#define TCGEN05_RELINQUISH_CG2() \
    asm volatile("tcgen05.relinquish_alloc_permit.cta_group::2.sync.aligned;")
#define TCGEN05_DEALLOC_CG2(tmem, nCols) \
    asm volatile("tcgen05.dealloc.cta_group::2.sync.aligned.b32 %0, %1;" :: "r"(tmem), "r"((uint32_t)(nCols)))
// cg2 commit, multicast to both CTAs' mbarrier at the same offset
#define TCGEN05_COMMIT_MC_CG2(mbar, mask) \
    asm volatile("tcgen05.commit.cta_group::2.mbarrier::arrive::one.shared::cluster.multicast::cluster.b64 [%0], %1;" \
                 :: "r"((uint32_t)(mbar)), "h"((uint16_t)(mask)) : "memory")
#define TCGEN05_WAIT_LD() asm volatile("tcgen05.wait::ld.sync.aligned;" ::: "memory")
#define TCGEN05_FENCE_BEFORE() asm volatile("tcgen05.fence::before_thread_sync;" ::: "memory")
#define TCGEN05_FENCE_AFTER()  asm volatile("tcgen05.fence::after_thread_sync;" ::: "memory")

// cg2 tf32 SS MMA: M=256 across the pair; A/B halves read from both CTAs' SMEM
// at the same descriptor offset. Issued by leader only.
__device__ __forceinline__ void mma_tf32_ss_cg2(uint32_t d_tmem, uint64_t a_desc, uint64_t b_desc,
                                                uint32_t idesc, uint32_t enable_d) {
    asm volatile(
        "{\n\t.reg .pred p;\n\t"
        "setp.ne.u32 p, %5, 0;\n\t"
        "tcgen05.mma.cta_group::2.kind::tf32 [%0], %1, %2, %3, "
        "{%4, %4, %4, %4, %4, %4, %4, %4}, p;\n\t}"
        :: "r"(d_tmem), "l"(a_desc), "l"(b_desc), "r"(idesc), "r"(0u), "r"(enable_d)
        : "memory");
}

// cg2 TMA loads: each CTA loads into its OWN smem; complete_tx is redirected to
// the LEADER CTA's barrier (clear the cluster-rank bit, bit 24).
#define TMA_LOAD_2D_CG2(smem_addr, tmap, x, y, mbar) \
    asm volatile("{\n\t.reg .b32 lb;\n\t" \
                 "and.b32 lb, %4, 0xFEFFFFFF;\n\t" \
                 "cp.async.bulk.tensor.2d.cta_group::2.shared::cluster.global.tile.mbarrier::complete_tx::bytes " \
                 "[%0], [%1, {%2, %3}], [lb];\n\t}" \
                 :: "r"((uint32_t)(smem_addr)), "l"(tmap), "r"((int)(x)), "r"((int)(y)), \
                    "r"((uint32_t)(mbar)) : "memory")

#define TMA_LOAD_3D_CG2(smem_addr, tmap, x, y, z, mbar) \
    asm volatile("{\n\t.reg .b32 lb;\n\t" \
                 "and.b32 lb, %5, 0xFEFFFFFF;\n\t" \
                 "cp.async.bulk.tensor.3d.cta_group::2.shared::cluster.global.tile.mbarrier::complete_tx::bytes " \
                 "[%0], [%1, {%2, %3, %4}], [lb];\n\t}" \
                 :: "r"((uint32_t)(smem_addr)), "l"(tmap), "r"((int)(x)), "r"((int)(y)), \
                    "r"((int)(z)), "r"((uint32_t)(mbar)) : "memory")

#define TCGEN05_LD_32X32B_X32(r, tmem_addr) \
    asm volatile( \
        "tcgen05.ld.sync.aligned.32x32b.x32.b32 " \
        "{%0, %1, %2, %3, %4, %5, %6, %7, " \
        " %8, %9, %10, %11, %12, %13, %14, %15, " \
        " %16, %17, %18, %19, %20, %21, %22, %23, " \
        " %24, %25, %26, %27, %28, %29, %30, %31}, [%32];" \
        : "=r"((r)[0]),  "=r"((r)[1]),  "=r"((r)[2]),  "=r"((r)[3]), \
          "=r"((r)[4]),  "=r"((r)[5]),  "=r"((r)[6]),  "=r"((r)[7]), \
          "=r"((r)[8]),  "=r"((r)[9]),  "=r"((r)[10]), "=r"((r)[11]), \
          "=r"((r)[12]), "=r"((r)[13]), "=r"((r)[14]), "=r"((r)[15]), \
          "=r"((r)[16]), "=r"((r)[17]), "=r"((r)[18]), "=r"((r)[19]), \
          "=r"((r)[20]), "=r"((r)[21]), "=r"((r)[22]), "=r"((r)[23]), \
          "=r"((r)[24]), "=r"((r)[25]), "=r"((r)[26]), "=r"((r)[27]), \
          "=r"((r)[28]), "=r"((r)[29]), "=r"((r)[30]), "=r"((r)[31]) \
        : "r"(tmem_addr))

#endif  // GG_HAS_TCGEN05

// ---------------- schedule (device-side, from seg_indptr) ----------------
// Pair-tile schedule: one cg2 tile = 256 M-rows (2 adjacent BM=128 subtiles of
// the SAME segment, so both ranks share the expert) x one BN=512 N-tile.
struct Sched {
    int p[E_ + 1];
    int widx[E_];
    int mt[E_];            // m-subtiles (BM=128) per segment
    int pstart[E_ + 1];    // pair-start per segment
    int total_ptiles;      // total pair-tiles (pairs * NT)
};

// seg_indptr / weight_indices may be int64 or int32 (jax x64 flag) — validate.
__device__ __forceinline__ void build_sched(const void* segp, const void* widxp, Sched& S) {
    const long long* p64 = (const long long*)segp;
    const int*       p32 = (const int*)segp;
    bool ok64 = true;
    long long prev = 0;
    #pragma unroll
    for (int i = 0; i <= E_; i++) {
        long long v = p64[i];
        if (v < prev || v < 0 || v > (long long)T_) ok64 = false;
        prev = v;
    }
    if (p64[0] != 0 || p64[E_] != (long long)T_) ok64 = false;
    #pragma unroll
    for (int i = 0; i <= E_; i++) S.p[i] = ok64 ? (int)p64[i] : p32[i];

    const long long* w64 = (const long long*)widxp;
    const int*       w32 = (const int*)widxp;
    bool wok = true;
    #pragma unroll
    for (int i = 0; i < E_; i++) {
        long long v = w64[i];
        if (v < 0 || v >= E_) wok = false;
    }
    #pragma unroll
    for (int i = 0; i < E_; i++) S.widx[i] = wok ? (int)w64[i] : w32[i];

    int pm = 0;
    #pragma unroll
    for (int i = 0; i < E_; i++) {
        S.pstart[i] = pm;
        S.mt[i] = (S.p[i + 1] - S.p[i] + BM - 1) / BM;
        pm += (S.mt[i] + 1) / 2;   // cg2 pairs per segment
    }
    S.pstart[E_] = pm;
    S.total_ptiles = pm * NT;
}

// m_base is the PAIR base; rank r covers rows [m_base + r*BM, +BM). Rows >= m_end
// (odd segment tail) are computed on garbage/zero-fill and masked in the epilogue.
__device__ __forceinline__ void decode_ptile(const Sched& S, int pt,
                                             int& m_base, int& m_end, int& expert, int& n_base) {
    int pm = pt / NT;
    int nt = pt - pm * NT;
    n_base = nt * BN;
    int seg = 0;
    #pragma unroll
    for (int i = 1; i < E_; i++)
        if (pm >= S.pstart[i]) seg = i;
    int local = pm - S.pstart[seg];
    m_base = S.p[seg] + 2 * local * BM;
    m_end  = S.p[seg + 1];
    expert = S.widx[seg];
}

// ---------------- init kernel: reset the dynamic-scheduler ticket ----------------
__global__ void gg_init_kernel() { g_ticket = 0; }

// ---------------- kernel ----------------
__global__ void __launch_bounds__(NTHREADS, OCC) __cluster_dims__(CLUSTER, 1, 1)
gg_tf32_kernel(const __grid_constant__ CUtensorMap tma_a,
               const __grid_constant__ CUtensorMap tma_b,
               const float* __restrict__ a_raw,
               const float* __restrict__ b_raw,
               const void* __restrict__ segp,
               const void* __restrict__ widxp,
               float* __restrict__ out) {
#if GG_HAS_TCGEN05
    extern __shared__ char smem[];
    const uint32_t sb = smem_to_u32(smem);
    const int tid  = threadIdx.x;
    const int wid  = tid >> 5;
    const int lane = tid & 31;

    uint32_t rank;
    asm("mov.u32 %0, %%cluster_ctarank;" : "=r"(rank));

    Sched S;
    build_sched(segp, widxp, S);

    if (wid == 4) {
        TCGEN05_ALLOC_CG2(sb + SM_TMEM, TMEM_COLS);
        TCGEN05_RELINQUISH_CG2();
    }
    if (tid == 0) {
        #pragma unroll
        for (int s = 0; s < STAGES; s++) {
            MBARRIER_INIT(sb + SM_FULL + 8 * s, 1);   // leader's arrive.expect_tx
            MBARRIER_INIT(sb + SM_MMAD + 8 * s, 1);   // cg2 multicast commit (one arrive/CTA)
        }
        MBARRIER_INIT(sb + SM_TILED0, 1);
        MBARRIER_INIT(sb + SM_TILED1, 1);
        MBARRIER_INIT(sb + SM_BUFF0, 8);              // 4 epi warps x 2 CTAs -> leader's
        MBARRIER_INIT(sb + SM_BUFF1, 8);
        #pragma unroll
        for (int s = 0; s < WSLOTS; s++) {
            MBARRIER_INIT(sb + SM_WORKV + 8 * s, 1);          // fetcher publish
            MBARRIER_INIT(sb + SM_WORKF + 8 * s, WFREE_COUNT); // consumers' reads (leader's used)
        }
    }
    __syncthreads();
    // peer barriers must be live before cg2 TMA / multicast commits / ring stores target them
    CLUSTER_SYNC();

    uint32_t tmem;
    asm volatile("ld.shared.b32 %0, [%1];" : "=r"(tmem) : "r"(sb + SM_TMEM));

    const int TP = S.total_ptiles;

    // ================= TMA producer: warp 5, one thread, BOTH ranks =================
    // Rank0 thread doubles as the dynamic scheduler: it pulls tickets from the
    // global counter and publishes tile ids into both CTAs' work rings.
    // Per stage per CTA: A half (16KB) + two 128-row B sub-panels (2x16KB).
    if (wid == 5 && lane == 0) {
        int ws = 0, wph = 1;   // fresh free-barriers pass parity-1 wait
        int st = 0, ph = 1;    // stage-free cursor
        for (;;) {
            int t;
            if (rank == 0) {
                // wait until every consumer has read this ring slot's previous value
                MBARRIER_WAIT_PARITY_RELAXED(sb + SM_WORKF + 8 * ws, wph);
                int tk = atomicAdd(&g_ticket, 1);
                t = (tk < TP) ? tk : -1;
                RING_PUBLISH(sb + SM_RING + 4 * ws, sb + SM_WORKV + 8 * ws, t);
            } else {
                MBARRIER_WAIT_PARITY_ACQC(sb + SM_WORKV + 8 * ws, wph ^ 1);
                asm volatile("ld.shared.b32 %0, [%1];" : "=r"(t) : "r"(sb + SM_RING + 4 * ws));
                MBARRIER_ARRIVE_RANK0(sb + SM_WORKF + 8 * ws);
            }
            if (++ws == WSLOTS) { ws = 0; wph ^= 1; }
            if (t < 0) break;

            int m_base, m_end, expert, n_base;
            decode_ptile(S, t, m_base, m_end, expert, n_base);
            const int my_m  = m_base + (int)rank * BM;
            const int my_n0 = n_base + (int)rank * 128;          // N-half 0 sub-panel rows
            const int my_n1 = n_base + MMA_N + (int)rank * 128;  // N-half 1 sub-panel rows
            for (int kc = 0; kc < KCHUNKS; kc++) {
                MBARRIER_WAIT_PARITY_RELAXED(sb + SM_MMAD + 8 * st, ph);
                if (rank == 0) {
                    MBARRIER_EXPECT_TX(sb + SM_FULL + 8 * st, (uint32_t)STAGE_TX);
                }
                TMA_LOAD_2D_CG2(sb + A_OFF(st), &tma_a, kc * BK, my_m, sb + SM_FULL + 8 * st);
                TMA_LOAD_3D_CG2(sb + B_OFF(st),         &tma_b, kc * BK, my_n0, expert, sb + SM_FULL + 8 * st);
                TMA_LOAD_3D_CG2(sb + B_OFF(st) + B_SUB, &tma_b, kc * BK, my_n1, expert, sb + SM_FULL + 8 * st);
                if (++st == STAGES) { st = 0; ph ^= 1; }
            }
        }
    }

    // ================= MMA issue: warp 4, one thread, LEADER only =================
    // Per kchunk: two N=256 cg2 MMAs (cols 0-255 and 256-511) share the A stage.
    // kc=0 peeled: per-half accumulator handoff (BUFF0 then BUFF1).
    // kc=63 peeled: half0's MMAs then TILED0 commit (epilogue starts draining
    // half0 while half1's last MMAs still execute), then half1 + TILED1.
    if (rank == 0 && wid == 4 && lane == 0) {
        uint64_t adesc[STAGES], bdesc0[STAGES], bdesc1[STAGES];
        #pragma unroll
        for (int s = 0; s < STAGES; s++) {
            adesc[s]  = MAKE_SMEM_DESC(sb + A_OFF(s));
            bdesc0[s] = MAKE_SMEM_DESC(sb + B_OFF(s));
            bdesc1[s] = MAKE_SMEM_DESC(sb + B_OFF(s) + B_SUB);
        }
        int ws = 0, wph = 0;  // work-ring consumer cursor
        int st = 0, ph = 0;   // full-wait cursor
        int bufph = 1;        // accumulator-free cursor (passes immediately on tile 0)
        for (;;) {
            int t;
            MBARRIER_WAIT_PARITY_ACQC(sb + SM_WORKV + 8 * ws, wph);
            asm volatile("ld.shared.b32 %0, [%1];" : "=r"(t) : "r"(sb + SM_RING + 4 * ws));
            MBARRIER_ARRIVE(sb + SM_WORKF + 8 * ws);
            if (++ws == WSLOTS) { ws = 0; wph ^= 1; }
            if (t < 0) break;

            // ---- peeled kc = 0: per-half accumulator handoff ----
            MBARRIER_WAIT_PARITY_RELAXED(sb + SM_FULL + 8 * st, ph);
            {
                uint64_t ad = adesc[st], bd0 = bdesc0[st], bd1 = bdesc1[st];
                MBARRIER_WAIT_PARITY(sb + SM_BUFF0, bufph);   // half0 cols free
                TCGEN05_FENCE_AFTER();
                mma_tf32_ss_cg2(tmem, ad + 0, bd0 + 0, IDESC, 0u);
                mma_tf32_ss_cg2(tmem, ad + 2, bd0 + 2, IDESC, 1u);
                mma_tf32_ss_cg2(tmem, ad + 4, bd0 + 4, IDESC, 1u);
                mma_tf32_ss_cg2(tmem, ad + 6, bd0 + 6, IDESC, 1u);
                MBARRIER_WAIT_PARITY(sb + SM_BUFF1, bufph);   // half1 cols free
                TCGEN05_FENCE_AFTER();
                mma_tf32_ss_cg2(tmem + MMA_N, ad + 0, bd1 + 0, IDESC, 0u);
                mma_tf32_ss_cg2(tmem + MMA_N, ad + 2, bd1 + 2, IDESC, 1u);
                mma_tf32_ss_cg2(tmem + MMA_N, ad + 4, bd1 + 4, IDESC, 1u);
                mma_tf32_ss_cg2(tmem + MMA_N, ad + 6, bd1 + 6, IDESC, 1u);
                TCGEN05_COMMIT_MC_CG2(sb + SM_MMAD + 8 * st, 0x3);
                if (++st == STAGES) { st = 0; ph ^= 1; }
            }
            bufph ^= 1;

            // ---- kc = 1..62: branch-free interleaved hot loop (R10 mainloop) ----
            for (int kc = 1; kc < KCHUNKS - 1; kc++) {
                MBARRIER_WAIT_PARITY_RELAXED(sb + SM_FULL + 8 * st, ph);
                uint64_t ad = adesc[st], bd0 = bdesc0[st], bd1 = bdesc1[st];
                mma_tf32_ss_cg2(tmem,         ad + 0, bd0 + 0, IDESC, 1u);
                mma_tf32_ss_cg2(tmem + MMA_N, ad + 0, bd1 + 0, IDESC, 1u);
                mma_tf32_ss_cg2(tmem,         ad + 2, bd0 + 2, IDESC, 1u);
                mma_tf32_ss_cg2(tmem + MMA_N, ad + 2, bd1 + 2, IDESC, 1u);
                mma_tf32_ss_cg2(tmem,         ad + 4, bd0 + 4, IDESC, 1u);
                mma_tf32_ss_cg2(tmem + MMA_N, ad + 4, bd1 + 4, IDESC, 1u);
                mma_tf32_ss_cg2(tmem,         ad + 6, bd0 + 6, IDESC, 1u);
                mma_tf32_ss_cg2(tmem + MMA_N, ad + 6, bd1 + 6, IDESC, 1u);
                // stage consumed -> free in BOTH CTAs
                TCGEN05_COMMIT_MC_CG2(sb + SM_MMAD + 8 * st, 0x3);
                if (++st == STAGES) { st = 0; ph ^= 1; }
            }

            // ---- peeled kc = 63: half0 complete first, commit TILED0 early ----
            MBARRIER_WAIT_PARITY_RELAXED(sb + SM_FULL + 8 * st, ph);
            {
                uint64_t ad = adesc[st], bd0 = bdesc0[st], bd1 = bdesc1[st];
                mma_tf32_ss_cg2(tmem, ad + 0, bd0 + 0, IDESC, 1u);
                mma_tf32_ss_cg2(tmem, ad + 2, bd0 + 2, IDESC, 1u);
                mma_tf32_ss_cg2(tmem, ad + 4, bd0 + 4, IDESC, 1u);
                mma_tf32_ss_cg2(tmem, ad + 6, bd0 + 6, IDESC, 1u);
                // half0 fully accumulated once all prior (in-order) MMAs finish
                TCGEN05_COMMIT_MC_CG2(sb + SM_TILED0, 0x3);
                mma_tf32_ss_cg2(tmem + MMA_N, ad + 0, bd1 + 0, IDESC, 1u);
                mma_tf32_ss_cg2(tmem + MMA_N, ad + 2, bd1 + 2, IDESC, 1u);
                mma_tf32_ss_cg2(tmem + MMA_N, ad + 4, bd1 + 4, IDESC, 1u);
                mma_tf32_ss_cg2(tmem + MMA_N, ad + 6, bd1 + 6, IDESC, 1u);
                TCGEN05_COMMIT_MC_CG2(sb + SM_MMAD + 8 * st, 0x3);
                TCGEN05_COMMIT_MC_CG2(sb + SM_TILED1, 0x3);
                if (++st == STAGES) { st = 0; ph ^= 1; }
            }
        }
    }

    // ================= Epilogue: warps 0-3, BOTH ranks =================
    // Each CTA's TMEM holds its own 128 rows of the M=256 x N=512 accumulator.
    // Drain half0 as soon as TILED0 fires (overlapping half1's last MMAs),
    // release BUFF0, then drain half1 and release BUFF1.
    if (wid < 4) {
        int ws = 0, wph = 0;  // work-ring consumer cursor
        int tph = 0;
        for (;;) {
            int t;
            MBARRIER_WAIT_PARITY_ACQC(sb + SM_WORKV + 8 * ws, wph);
            asm volatile("ld.shared.b32 %0, [%1];" : "=r"(t) : "r"(sb + SM_RING + 4 * ws));
            if (lane == 0) {
                if (rank == 0) { MBARRIER_ARRIVE(sb + SM_WORKF + 8 * ws); }
                else           { MBARRIER_ARRIVE_RANK0(sb + SM_WORKF + 8 * ws); }
            }
            if (++ws == WSLOTS) { ws = 0; wph ^= 1; }
            if (t < 0) break;

            int m_base, m_end, expert, n_base;
            decode_ptile(S, t, m_base, m_end, expert, n_base);

            int row = m_base + (int)rank * BM + wid * 32 + lane;
            bool valid = (row < m_end);
            float* orow = out + (size_t)row * N_ + n_base;

            // ---- half0: chunks 0-7 ----
            MBARRIER_WAIT_PARITY(sb + SM_TILED0, tph);
            TCGEN05_FENCE_AFTER();
            {
                uint32_t ra[32], rb[32];
                TCGEN05_LD_32X32B_X32(ra, tmem + 0 * 32);
                #pragma unroll
                for (int c = 0; c < 8; c++) {
                    TCGEN05_WAIT_LD();
                    uint32_t* cur = (c & 1) ? rb : ra;
                    uint32_t* nxt = (c & 1) ? ra : rb;
                    if (c < 7) TCGEN05_LD_32X32B_X32(nxt, tmem + (c + 1) * 32);
                    if (valid) {
                        float4* dst = (float4*)(orow + c * 32);
                        #pragma unroll
                        for (int j = 0; j < 8; j++) {
                            float4 v;
                            v.x = __uint_as_float(cur[4 * j + 0]);
                            v.y = __uint_as_float(cur[4 * j + 1]);
                            v.z = __uint_as_float(cur[4 * j + 2]);
                            v.w = __uint_as_float(cur[4 * j + 3]);
                            dst[j] = v;
                        }
                    }
                }
                TCGEN05_FENCE_BEFORE();
                if (lane == 0) MBARRIER_ARRIVE_RANK0(sb + SM_BUFF0);
            }

            // ---- half1: chunks 8-15 ----
            MBARRIER_WAIT_PARITY(sb + SM_TILED1, tph);
            TCGEN05_FENCE_AFTER();
            {
                uint32_t ra[32], rb[32];
                TCGEN05_LD_32X32B_X32(ra, tmem + 8 * 32);
                #pragma unroll
                for (int c = 0; c < 8; c++) {
                    TCGEN05_WAIT_LD();
                    uint32_t* cur = (c & 1) ? rb : ra;
                    uint32_t* nxt = (c & 1) ? ra : rb;
                    if (c < 7) TCGEN05_LD_32X32B_X32(nxt, tmem + (9 + c) * 32);
                    if (valid) {
                        float4* dst = (float4*)(orow + (8 + c) * 32);
                        #pragma unroll
                        for (int j = 0; j < 8; j++) {
                            float4 v;
                            v.x = __uint_as_float(cur[4 * j + 0]);
                            v.y = __uint_as_float(cur[4 * j + 1]);
                            v.z = __uint_as_float(cur[4 * j + 2]);
                            v.w = __uint_as_float(cur[4 * j + 3]);
                            dst[j] = v;
                        }
                    }
                }
                TCGEN05_FENCE_BEFORE();
                if (lane == 0) MBARRIER_ARRIVE_RANK0(sb + SM_BUFF1);
            }
            tph ^= 1;
        }
    }

    __syncthreads();
    // no CTA may exit while peer traffic (cg2 TMA / commits / ring stores) is in flight
    CLUSTER_SYNC();
    if (wid == 4) {
        TCGEN05_DEALLOC_CG2(tmem, TMEM_COLS);
    }
    CLUSTER_SYNC();
#else
    // ---------- SIMT fallback (only runs if no sm_103a SASS exists) ----------
    Sched S;
    build_sched(segp, widxp, S);
    const int tid = threadIdx.x;
    int total_work = T_ * (N_ / 4);
    for (int w = blockIdx.x * blockDim.x + tid; w < total_work; w += gridDim.x * blockDim.x) {
        int rowi = w / (N_ / 4);
        int n4   = (w - rowi * (N_ / 4)) * 4;
        int seg = 0;
        #pragma unroll
        for (int i = 1; i < E_; i++)
            if (rowi >= S.p[i]) seg = i;
        int expert = S.widx[seg];
        const float4* arow = (const float4*)(a_raw + (size_t)rowi * K_);
        const float4* b0 = (const float4*)(b_raw + ((size_t)expert * N_ + n4 + 0) * K_);
        const float4* b1 = (const float4*)(b_raw + ((size_t)expert * N_ + n4 + 1) * K_);
        const float4* b2 = (const float4*)(b_raw + ((size_t)expert * N_ + n4 + 2) * K_);
        const float4* b3 = (const float4*)(b_raw + ((size_t)expert * N_ + n4 + 3) * K_);
        float s0 = 0.f, s1 = 0.f, s2 = 0.f, s3 = 0.f;
        for (int k = 0; k < K_ / 4; k++) {
            float4 av = __ldg(arow + k);
            float4 v0 = __ldg(b0 + k), v1 = __ldg(b1 + k), v2 = __ldg(b2 + k), v3 = __ldg(b3 + k);
            s0 += av.x * v0.x + av.y * v0.y + av.z * v0.z + av.w * v0.w;
            s1 += av.x * v1.x + av.y * v1.y + av.z * v1.z + av.w * v1.w;
            s2 += av.x * v2.x + av.y * v2.y + av.z * v2.z + av.w * v2.w;
            s3 += av.x * v3.x + av.y * v3.y + av.z * v3.z + av.w * v3.w;
        }
        float4 o; o.x = s0; o.y = s1; o.z = s2; o.w = s3;
        *(float4*)(out + (size_t)rowi * N_ + n4) = o;
    }
#endif
}

// ---------------- host launch ----------------
typedef CUresult (*cuTensorMapEncodeTiled_t)(
    CUtensorMap*, CUtensorMapDataType, cuuint32_t, void*,
    const cuuint64_t*, const cuuint64_t*, const cuuint32_t*, const cuuint32_t*,
    CUtensorMapInterleave, CUtensorMapSwizzle, CUtensorMapL2promotion, CUtensorMapFloatOOBfill);

extern "C" void kernel_launch(void* const* d_in, const int* in_sizes, int n_in,
                              void* d_out, int out_size) {
    const float* a = (const float*)d_in[0];
    const float* b = (const float*)d_in[1];
    // d_in[2] = preallocated c buffer (unused; result goes to d_out)
    // d_in[3] = batch_size, d_in[4] = weight_column_major (constants for this problem)
    const void* segp  = d_in[5];
    const void* widxp = d_in[6];

    // Resolve driver-API tensormap encoder through the runtime (no -lcuda needed).
    void* fp = nullptr;
    cudaDriverEntryPointQueryResult qres;
    cudaGetDriverEntryPoint("cuTensorMapEncodeTiled", &fp, cudaEnableDefault, &qres);
    if (!fp) return;
    cuTensorMapEncodeTiled_t encode = (cuTensorMapEncodeTiled_t)fp;

    CUtensorMap tma_a, tma_b;
    {
        cuuint64_t dims[2]    = {(cuuint64_t)K_, (cuuint64_t)T_};
        cuuint64_t strides[1] = {(cuuint64_t)K_ * sizeof(float)};
        cuuint32_t box[2]     = {BK, BM};
        cuuint32_t es[2]      = {1, 1};
        encode(&tma_a, CU_TENSOR_MAP_DATA_TYPE_FLOAT32, 2, (void*)a,
               dims, strides, box, es,
               CU_TENSOR_MAP_INTERLEAVE_NONE, CU_TENSOR_MAP_SWIZZLE_128B,
               CU_TENSOR_MAP_L2_PROMOTION_L2_128B, CU_TENSOR_MAP_FLOAT_OOB_FILL_NONE);
    }
    {
        cuuint64_t dims[3]    = {(cuuint64_t)K_, (cuuint64_t)N_, (cuuint64_t)E_};
        cuuint64_t strides[2] = {(cuuint64_t)K_ * sizeof(float),
                                 (cuuint64_t)N_ * (cuuint64_t)K_ * sizeof(float)};
        cuuint32_t box[3]     = {BK, 128, 1};
        cuuint32_t es[3]      = {1, 1, 1};
        encode(&tma_b, CU_TENSOR_MAP_DATA_TYPE_FLOAT32, 3, (void*)b,
               dims, strides, box, es,
               CU_TENSOR_MAP_INTERLEAVE_NONE, CU_TENSOR_MAP_SWIZZLE_128B,
               CU_TENSOR_MAP_L2_PROMOTION_L2_128B, CU_TENSOR_MAP_FLOAT_OOB_FILL_NONE);
    }

    cudaFuncSetAttribute(gg_tf32_kernel, cudaFuncAttributeMaxDynamicSharedMemorySize, SMEM_TOTAL);

    int dev = 0, sms = 148;
    cudaGetDevice(&dev);
    cudaDeviceGetAttribute(&sms, cudaDevAttrMultiProcessorCount, dev);

    int grid = OCC * sms;       // one CTA per SM
    grid &= ~(CLUSTER - 1);     // grid must be a multiple of the cluster size

    gg_init_kernel<<<1, 1>>>();  // reset the dynamic-scheduler ticket (every replay)
    gg_tf32_kernel<<<grid, NTHREADS, SMEM_TOTAL>>>(tma_a, tma_b, a, b, segp, widxp, (float*)d_out);
}

// round 15
// speedup vs baseline: 1.0279x; 1.0279x over previous
#include <cuda_runtime.h>
#include <cuda.h>
#include <cstdint>

// ---------------- problem constants (fixed for this dataset) ----------------
#define T_   8192
#define K_   2048
#define N_   4096
#define E_   8

#define BM       128         // M rows per CTA; cg2 pair covers 256
#define BN       512         // N per cg2 tile (2 x N=256 MMAs sharing one A stage)
#define MMA_N    256         // tcgen05 max N per instruction
#define BK       32          // 32 fp32 = 128B = one SW128 atom row
#define STAGES   4           // 48KB/stage/CTA -> 197KB smem (OCC=1)
#define KCHUNKS  (K_ / BK)   // 64
#define NT       (N_ / BN)   // 8
#define NTHREADS 192         // warps 0-3 epilogue, warp 4 MMA (leader), warp 5 TMA
#define CLUSTER  2
#define OCC      1
#define WSLOTS   4           // work-ring depth (dynamic tile scheduler)
#define HBOX     64          // TMA box height: 128-row panels loaded as 2x64-row commands

// Arch-feature gate: tcgen05/TMEM asm may only appear in PTX whose .target is
// sm_103a/sm_100a (or family). The harness also builds a plain compute_103 PTX
// stage, which must get a tcgen05-free body or ptxas aborts.
#if defined(__CUDA_ARCH_FEAT_SM103_ALL) || defined(__CUDA_ARCH_FEAT_SM100_ALL) || \
    (defined(__CUDA_ARCH_SPECIFIC__) && (__CUDA_ARCH_SPECIFIC__ >= 1000)) || \
    (defined(__CUDA_ARCH_FAMILY_SPECIFIC__) && (__CUDA_ARCH_FAMILY_SPECIFIC__ >= 1000))
#define GG_HAS_TCGEN05 1
#else
#define GG_HAS_TCGEN05 0
#endif

// global ticket for dynamic tile scheduling (reset by gg_init each launch)
__device__ int g_ticket;

// ---------------- SMEM layout ----------------
#define SM_TMEM    0
#define SM_FULL    64                      // 4 mbarriers (stage full; leader's used by MMA)
#define SM_MMAD    128                     // 4 mbarriers (stage consumed; cg2 multicast commit)
#define SM_TILED   192                     // 1 mbarrier  (tile done; cg2 multicast commit)
#define SM_BUFF0   208                     // 1 mbarrier  (N-half0 accumulator freed; 8 -> leader)
#define SM_BUFF1   216                     // 1 mbarrier  (N-half1 accumulator freed; 8 -> leader)
#define SM_WORKV   256                     // 4 mbarriers (work slot valid)
#define SM_WORKF   320                     // 4 mbarriers (work slot free; count=10, leader only)
#define SM_RING    384                     // 4 ints (tile ids; -1 = sentinel)
#define SM_STAGE0  1024
#define A_BYTES    (BM * 128)              // 16384
#define HBOX_BYTES (HBOX * 128)            // 8192: one 64-row TMA command
#define B_BYTES    (2 * 128 * 128)         // 32768: two 128-row sub-panels per CTA
#define B_SUB      16384                   // offset of N-half-1 sub-panel within B
#define STAGE_BYTES (A_BYTES + B_BYTES)    // 49152 per CTA
#define STAGE_TX    (2 * STAGE_BYTES)      // 98304: both CTAs complete into leader's FULL
#define A_OFF(s)   (SM_STAGE0 + (s) * STAGE_BYTES)
#define B_OFF(s)   (A_OFF(s) + A_BYTES)
#define SMEM_TOTAL (SM_STAGE0 + STAGES * STAGE_BYTES)   // 197632 < 227KB

#define TMEM_COLS  512       // 256x512 fp32 accumulator (half0: cols 0-255, half1: 256-511)

// free-barrier arrival count: leader MMA (1) + 4 epi warps x 2 CTAs (8) + rank1 TMA (1)
#define WFREE_COUNT 10

// idesc: d=F32(1), a=TF32(2), b=TF32(2), N(=256)>>3 @17, M(=256)>>4 @24
static constexpr uint32_t IDESC =
    (1u << 4) | (2u << 7) | (2u << 10) | ((MMA_N / 8) << 17) | ((256 / 16) << 24);

// SW128 K-major smem descriptor base (Blackwell v1, LBO=1, SBO=64)
static constexpr uint64_t SMEM_DESC_BASE_SW128 =
    (uint64_t(2) << 61) | (uint64_t(1) << 46) | (uint64_t(64) << 32) | (uint64_t(1) << 16);
#define MAKE_SMEM_DESC(base_addr) \
    (SMEM_DESC_BASE_SW128 | ((uint64_t)((base_addr) >> 4) & 0x3FFF))

// ---------------- PTX helpers ----------------
__device__ __forceinline__ uint32_t smem_to_u32(const void* p) {
    uint32_t a;
    asm("{ .reg .u64 t; cvta.to.shared.u64 t, %1; cvt.u32.u64 %0, t; }" : "=r"(a) : "l"(p));
    return a;
}

#define MBARRIER_INIT(mbar, count) \
    asm volatile("mbarrier.init.shared.b64 [%0], %1;" :: "r"((uint32_t)(mbar)), "r"((uint32_t)(count)) : "memory")

#define MBARRIER_EXPECT_TX(mbar, tx) \
    asm volatile("mbarrier.arrive.expect_tx.shared.b64 _, [%0], %1;" :: "r"((uint32_t)(mbar)), "r"((uint32_t)(tx)) : "memory")

#define MBARRIER_ARRIVE(mbar) \
    asm volatile("mbarrier.arrive.shared.b64 _, [%0];" :: "r"((uint32_t)(mbar)) : "memory")

// Arrive on the leader CTA's (cluster rank 0) mbarrier at the same SMEM offset.
#define MBARRIER_ARRIVE_RANK0(mbar) \
    asm volatile("{\n\t.reg .b32 ra;\n\t" \
                 "mapa.shared::cluster.u32 ra, %0, 0;\n\t" \
                 "mbarrier.arrive.shared::cluster.b64 _, [ra];\n\t}" \
                 :: "r"((uint32_t)(mbar)) : "memory")

// Publish a tile id into BOTH CTAs' ring slot and arrive on both valid barriers.
// Cluster-scope release so the peer's acquire-wait sees the store.
#define RING_PUBLISH(ring_addr, validbar, val) \
    asm volatile("{\n\t.reg .b32 ra, rb;\n\t" \
                 "st.shared.b32 [%0], %2;\n\t" \
                 "mapa.shared::cluster.u32 ra, %0, 1;\n\t" \
                 "st.shared::cluster.b32 [ra], %2;\n\t" \
                 "mbarrier.arrive.release.cta.shared::cta.b64 _, [%1];\n\t" \
                 "mapa.shared::cluster.u32 rb, %1, 1;\n\t" \
                 "mbarrier.arrive.release.cluster.shared::cluster.b64 _, [rb];\n\t}" \
                 :: "r"((uint32_t)(ring_addr)), "r"((uint32_t)(validbar)), "r"((int)(val)) : "memory")

#define MBARRIER_WAIT_PARITY(mbar, parity) do {                                   \
    uint32_t _m = (uint32_t)(mbar); uint32_t _p = (uint32_t)(parity);             \
    asm volatile(                                                                 \
        "{\n\t.reg .pred P1;\n\t"                                                 \
        "WL_%=:\n\t"                                                              \
        "mbarrier.try_wait.parity.acquire.cta.shared::cta.b64 P1, [%0], %1, 0x989680;\n\t" \
        "@P1 bra.uni WD_%=;\n\t"                                                  \
        "bra.uni WL_%=;\n\t"                                                      \
        "WD_%=:\n\t}"                                                             \
        :: "r"(_m), "r"(_p) : "memory");                                          \
} while (0)

// acquire at CLUSTER scope: consumer of ring values written by the peer CTA
#define MBARRIER_WAIT_PARITY_ACQC(mbar, parity) do {                              \
    uint32_t _m = (uint32_t)(mbar); uint32_t _p = (uint32_t)(parity);             \
    asm volatile(                                                                 \
        "{\n\t.reg .pred P1;\n\t"                                                 \
        "WL_%=:\n\t"                                                              \
        "mbarrier.try_wait.parity.acquire.cluster.shared::cta.b64 P1, [%0], %1, 0x989680;\n\t" \
        "@P1 bra.uni WD_%=;\n\t"                                                  \
        "bra.uni WL_%=;\n\t"                                                      \
        "WD_%=:\n\t}"                                                             \
        :: "r"(_m), "r"(_p) : "memory");                                          \
} while (0)

#define MBARRIER_WAIT_PARITY_RELAXED(mbar, parity) do {                           \
    uint32_t _m = (uint32_t)(mbar); uint32_t _p = (uint32_t)(parity);             \
    asm volatile(                                                                 \
        "{\n\t.reg .pred P1;\n\t"                                                 \
        "WL_%=:\n\t"                                                              \
        "mbarrier.try_wait.parity.relaxed.cta.shared::cta.b64 P1, [%0], %1, 0x989680;\n\t" \
        "@P1 bra.uni WD_%=;\n\t"                                                  \
        "bra.uni WL_%=;\n\t"                                                      \
        "WD_%=:\n\t}"                                                             \
        :: "r"(_m), "r"(_p) : "memory");                                          \
} while (0)

#define CLUSTER_SYNC() do { \
    asm volatile("barrier.cluster.arrive.aligned;" ::: "memory"); \
    asm volatile("barrier.cluster.wait.aligned;" ::: "memory"); \
} while (0)

#if GG_HAS_TCGEN05

#define TCGEN05_ALLOC_CG2(smem_result, nCols) \
    asm volatile("tcgen05.alloc.cta_group::2.sync.aligned.shared::cta.b32 [%0], %1;" \
                 :: "r"((uint32_t)(smem_result)), "r"((uint32_t)(nCols)) : "memory")
#define TCGEN05_RELINQUISH_CG2() \
    asm volatile("tcgen05.relinquish_alloc_permit.cta_group::2.sync.aligned;")
#define TCGEN05_DEALLOC_CG2(tmem, nCols) \
    asm volatile("tcgen05.dealloc.cta_group::2.sync.aligned.b32 %0, %1;" :: "r"(tmem), "r"((uint32_t)(nCols)))
// cg2 commit, multicast to both CTAs' mbarrier at the same offset
#define TCGEN05_COMMIT_MC_CG2(mbar, mask) \
    asm volatile("tcgen05.commit.cta_group::2.mbarrier::arrive::one.shared::cluster.multicast::cluster.b64 [%0], %1;" \
                 :: "r"((uint32_t)(mbar)), "h"((uint16_t)(mask)) : "memory")
#define TCGEN05_WAIT_LD() asm volatile("tcgen05.wait::ld.sync.aligned;" ::: "memory")
#define TCGEN05_FENCE_BEFORE() asm volatile("tcgen05.fence::before_thread_sync;" ::: "memory")
#define TCGEN05_FENCE_AFTER()  asm volatile("tcgen05.fence::after_thread_sync;" ::: "memory")

// cg2 tf32 SS MMA: M=256 across the pair; A/B halves read from both CTAs' SMEM
// at the same descriptor offset. Issued by leader only.
__device__ __forceinline__ void mma_tf32_ss_cg2(uint32_t d_tmem, uint64_t a_desc, uint64_t b_desc,
                                                uint32_t idesc, uint32_t enable_d) {
    asm volatile(
        "{\n\t.reg .pred p;\n\t"
        "setp.ne.u32 p, %5, 0;\n\t"
        "tcgen05.mma.cta_group::2.kind::tf32 [%0], %1, %2, %3, "
        "{%4, %4, %4, %4, %4, %4, %4, %4}, p;\n\t}"
        :: "r"(d_tmem), "l"(a_desc), "l"(b_desc), "r"(idesc), "r"(0u), "r"(enable_d)
        : "memory");
}

// cg2 TMA loads: each CTA loads into its OWN smem; complete_tx is redirected to
// the LEADER CTA's barrier (clear the cluster-rank bit, bit 24).
#define TMA_LOAD_2D_CG2(smem_addr, tmap, x, y, mbar) \
    asm volatile("{\n\t.reg .b32 lb;\n\t" \
                 "and.b32 lb, %4, 0xFEFFFFFF;\n\t" \
                 "cp.async.bulk.tensor.2d.cta_group::2.shared::cluster.global.tile.mbarrier::complete_tx::bytes " \
                 "[%0], [%1, {%2, %3}], [lb];\n\t}" \
                 :: "r"((uint32_t)(smem_addr)), "l"(tmap), "r"((int)(x)), "r"((int)(y)), \
                    "r"((uint32_t)(mbar)) : "memory")

#define TMA_LOAD_3D_CG2(smem_addr, tmap, x, y, z, mbar) \
    asm volatile("{\n\t.reg .b32 lb;\n\t" \
                 "and.b32 lb, %5, 0xFEFFFFFF;\n\t" \
                 "cp.async.bulk.tensor.3d.cta_group::2.shared::cluster.global.tile.mbarrier::complete_tx::bytes " \
                 "[%0], [%1, {%2, %3, %4}], [lb];\n\t}" \
                 :: "r"((uint32_t)(smem_addr)), "l"(tmap), "r"((int)(x)), "r"((int)(y)), \
                    "r"((int)(z)), "r"((uint32_t)(mbar)) : "memory")

#define TCGEN05_LD_32X32B_X32(r, tmem_addr) \
    asm volatile( \
        "tcgen05.ld.sync.aligned.32x32b.x32.b32 " \
        "{%0, %1, %2, %3, %4, %5, %6, %7, " \
        " %8, %9, %10, %11, %12, %13, %14, %15, " \
        " %16, %17, %18, %19, %20, %21, %22, %23, " \
        " %24, %25, %26, %27, %28, %29, %30, %31}, [%32];" \
        : "=r"((r)[0]),  "=r"((r)[1]),  "=r"((r)[2]),  "=r"((r)[3]), \
          "=r"((r)[4]),  "=r"((r)[5]),  "=r"((r)[6]),  "=r"((r)[7]), \
          "=r"((r)[8]),  "=r"((r)[9]),  "=r"((r)[10]), "=r"((r)[11]), \
          "=r"((r)[12]), "=r"((r)[13]), "=r"((r)[14]), "=r"((r)[15]), \
          "=r"((r)[16]), "=r"((r)[17]), "=r"((r)[18]), "=r"((r)[19]), \
          "=r"((r)[20]), "=r"((r)[21]), "=r"((r)[22]), "=r"((r)[23]), \
          "=r"((r)[24]), "=r"((r)[25]), "=r"((r)[26]), "=r"((r)[27]), \
          "=r"((r)[28]), "=r"((r)[29]), "=r"((r)[30]), "=r"((r)[31]) \
        : "r"(tmem_addr))

#endif  // GG_HAS_TCGEN05

// ---------------- schedule (device-side, from seg_indptr) ----------------
// Pair-tile schedule: one cg2 tile = 256 M-rows (2 adjacent BM=128 subtiles of
// the SAME segment, so both ranks share the expert) x one BN=512 N-tile.
struct Sched {
    int p[E_ + 1];
    int widx[E_];
    int mt[E_];            // m-subtiles (BM=128) per segment
    int pstart[E_ + 1];    // pair-start per segment
    int total_ptiles;      // total pair-tiles (pairs * NT)
};

// seg_indptr / weight_indices may be int64 or int32 (jax x64 flag) — validate.
__device__ __forceinline__ void build_sched(const void* segp, const void* widxp, Sched& S) {
    const long long* p64 = (const long long*)segp;
    const int*       p32 = (const int*)segp;
    bool ok64 = true;
    long long prev = 0;
    #pragma unroll
    for (int i = 0; i <= E_; i++) {
        long long v = p64[i];
        if (v < prev || v < 0 || v > (long long)T_) ok64 = false;
        prev = v;
    }
    if (p64[0] != 0 || p64[E_] != (long long)T_) ok64 = false;
    #pragma unroll
    for (int i = 0; i <= E_; i++) S.p[i] = ok64 ? (int)p64[i] : p32[i];

    const long long* w64 = (const long long*)widxp;
    const int*       w32 = (const int*)widxp;
    bool wok = true;
    #pragma unroll
    for (int i = 0; i < E_; i++) {
        long long v = w64[i];
        if (v < 0 || v >= E_) wok = false;
    }
    #pragma unroll
    for (int i = 0; i < E_; i++) S.widx[i] = wok ? (int)w64[i] : w32[i];

    int pm = 0;
    #pragma unroll
    for (int i = 0; i < E_; i++) {
        S.pstart[i] = pm;
        S.mt[i] = (S.p[i + 1] - S.p[i] + BM - 1) / BM;
        pm += (S.mt[i] + 1) / 2;   // cg2 pairs per segment
    }
    S.pstart[E_] = pm;
    S.total_ptiles = pm * NT;
}

// m_base is the PAIR base; rank r covers rows [m_base + r*BM, +BM). Rows >= m_end
// (odd segment tail) are computed on garbage/zero-fill and masked in the epilogue.
__device__ __forceinline__ void decode_ptile(const Sched& S, int pt,
                                             int& m_base, int& m_end, int& expert, int& n_base) {
    int pm = pt / NT;
    int nt = pt - pm * NT;
    n_base = nt * BN;
    int seg = 0;
    #pragma unroll
    for (int i = 1; i < E_; i++)
        if (pm >= S.pstart[i]) seg = i;
    int local = pm - S.pstart[seg];
    m_base = S.p[seg] + 2 * local * BM;
    m_end  = S.p[seg + 1];
    expert = S.widx[seg];
}

// ---------------- init kernel: reset the dynamic-scheduler ticket ----------------
__global__ void gg_init_kernel() { g_ticket = 0; }

// ---------------- kernel ----------------
__global__ void __launch_bounds__(NTHREADS, OCC) __cluster_dims__(CLUSTER, 1, 1)
gg_tf32_kernel(const __grid_constant__ CUtensorMap tma_a,
               const __grid_constant__ CUtensorMap tma_b,
               const float* __restrict__ a_raw,
               const float* __restrict__ b_raw,
               const void* __restrict__ segp,
               const void* __restrict__ widxp,
               float* __restrict__ out) {
#if GG_HAS_TCGEN05
    extern __shared__ char smem[];
    const uint32_t sb = smem_to_u32(smem);
    const int tid  = threadIdx.x;
    const int wid  = tid >> 5;
    const int lane = tid & 31;

    uint32_t rank;
    asm("mov.u32 %0, %%cluster_ctarank;" : "=r"(rank));

    Sched S;
    build_sched(segp, widxp, S);

    if (wid == 4) {
        TCGEN05_ALLOC_CG2(sb + SM_TMEM, TMEM_COLS);
        TCGEN05_RELINQUISH_CG2();
    }
    if (tid == 0) {
        #pragma unroll
        for (int s = 0; s < STAGES; s++) {
            MBARRIER_INIT(sb + SM_FULL + 8 * s, 1);   // leader's arrive.expect_tx
            MBARRIER_INIT(sb + SM_MMAD + 8 * s, 1);   // cg2 multicast commit (one arrive/CTA)
        }
        MBARRIER_INIT(sb + SM_TILED, 1);
        MBARRIER_INIT(sb + SM_BUFF0, 8);              // 4 epi warps x 2 CTAs -> leader's
        MBARRIER_INIT(sb + SM_BUFF1, 8);
        #pragma unroll
        for (int s = 0; s < WSLOTS; s++) {
            MBARRIER_INIT(sb + SM_WORKV + 8 * s, 1);          // fetcher publish
            MBARRIER_INIT(sb + SM_WORKF + 8 * s, WFREE_COUNT); // consumers' reads (leader's used)
        }
    }
    __syncthreads();
    // peer barriers must be live before cg2 TMA / multicast commits / ring stores target them
    CLUSTER_SYNC();

    uint32_t tmem;
    asm volatile("ld.shared.b32 %0, [%1];" : "=r"(tmem) : "r"(sb + SM_TMEM));

    const int TP = S.total_ptiles;

    // ================= TMA producer: warp 5, one thread, BOTH ranks =================
    // Rank0 thread doubles as the dynamic scheduler: it pulls tickets from the
    // global counter and publishes tile ids into both CTAs' work rings.
    // Per stage per CTA: six 64-row box commands (2xA, 4xB) — finer TMA request
    // granularity to raise command-level parallelism on the L2->SMEM path.
    if (wid == 5 && lane == 0) {
        int ws = 0, wph = 1;   // fresh free-barriers pass parity-1 wait
        int st = 0, ph = 1;    // stage-free cursor
        for (;;) {
            int t;
            if (rank == 0) {
                // wait until every consumer has read this ring slot's previous value
                MBARRIER_WAIT_PARITY_RELAXED(sb + SM_WORKF + 8 * ws, wph);
                int tk = atomicAdd(&g_ticket, 1);
                t = (tk < TP) ? tk : -1;
                RING_PUBLISH(sb + SM_RING + 4 * ws, sb + SM_WORKV + 8 * ws, t);
            } else {
                MBARRIER_WAIT_PARITY_ACQC(sb + SM_WORKV + 8 * ws, wph ^ 1);
                asm volatile("ld.shared.b32 %0, [%1];" : "=r"(t) : "r"(sb + SM_RING + 4 * ws));
                MBARRIER_ARRIVE_RANK0(sb + SM_WORKF + 8 * ws);
            }
            if (++ws == WSLOTS) { ws = 0; wph ^= 1; }
            if (t < 0) break;

            int m_base, m_end, expert, n_base;
            decode_ptile(S, t, m_base, m_end, expert, n_base);
            const int my_m  = m_base + (int)rank * BM;
            const int my_n0 = n_base + (int)rank * 128;          // N-half 0 sub-panel rows
            const int my_n1 = n_base + MMA_N + (int)rank * 128;  // N-half 1 sub-panel rows
            for (int kc = 0; kc < KCHUNKS; kc++) {
                MBARRIER_WAIT_PARITY_RELAXED(sb + SM_MMAD + 8 * st, ph);
                if (rank == 0) {
                    MBARRIER_EXPECT_TX(sb + SM_FULL + 8 * st, (uint32_t)STAGE_TX);
                }
                const uint32_t mb = sb + SM_FULL + 8 * st;
                const int x = kc * BK;
                // A panel: 2 x 64-row commands
                TMA_LOAD_2D_CG2(sb + A_OFF(st),              &tma_a, x, my_m,        mb);
                TMA_LOAD_2D_CG2(sb + A_OFF(st) + HBOX_BYTES, &tma_a, x, my_m + HBOX, mb);
                // B sub-panel 0: 2 x 64-row commands
                TMA_LOAD_3D_CG2(sb + B_OFF(st),              &tma_b, x, my_n0,        expert, mb);
                TMA_LOAD_3D_CG2(sb + B_OFF(st) + HBOX_BYTES, &tma_b, x, my_n0 + HBOX, expert, mb);
                // B sub-panel 1: 2 x 64-row commands
                TMA_LOAD_3D_CG2(sb + B_OFF(st) + B_SUB,              &tma_b, x, my_n1,        expert, mb);
                TMA_LOAD_3D_CG2(sb + B_OFF(st) + B_SUB + HBOX_BYTES, &tma_b, x, my_n1 + HBOX, expert, mb);
                if (++st == STAGES) { st = 0; ph ^= 1; }
            }
        }
    }

    // ================= MMA issue: warp 4, one thread, LEADER only =================
    // Per kchunk: two N=256 cg2 MMAs (cols 0-255 and 256-511) share the A stage.
    // kc=0 peeled: per-half accumulator handoff (BUFF0 then BUFF1).
    if (rank == 0 && wid == 4 && lane == 0) {
        uint64_t adesc[STAGES], bdesc0[STAGES], bdesc1[STAGES];
        #pragma unroll
        for (int s = 0; s < STAGES; s++) {
            adesc[s]  = MAKE_SMEM_DESC(sb + A_OFF(s));
            bdesc0[s] = MAKE_SMEM_DESC(sb + B_OFF(s));
            bdesc1[s] = MAKE_SMEM_DESC(sb + B_OFF(s) + B_SUB);
        }
        int ws = 0, wph = 0;  // work-ring consumer cursor
        int st = 0, ph = 0;   // full-wait cursor
        int bufph = 1;        // accumulator-free cursor (passes immediately on tile 0)
        for (;;) {
            int t;
            MBARRIER_WAIT_PARITY_ACQC(sb + SM_WORKV + 8 * ws, wph);
            asm volatile("ld.shared.b32 %0, [%1];" : "=r"(t) : "r"(sb + SM_RING + 4 * ws));
            MBARRIER_ARRIVE(sb + SM_WORKF + 8 * ws);
            if (++ws == WSLOTS) { ws = 0; wph ^= 1; }
            if (t < 0) break;

            // ---- peeled kc = 0: per-half accumulator handoff ----
            MBARRIER_WAIT_PARITY_RELAXED(sb + SM_FULL + 8 * st, ph);
            {
                uint64_t ad = adesc[st], bd0 = bdesc0[st], bd1 = bdesc1[st];
                MBARRIER_WAIT_PARITY(sb + SM_BUFF0, bufph);   // half0 cols free
                TCGEN05_FENCE_AFTER();
                mma_tf32_ss_cg2(tmem, ad + 0, bd0 + 0, IDESC, 0u);
                mma_tf32_ss_cg2(tmem, ad + 2, bd0 + 2, IDESC, 1u);
                mma_tf32_ss_cg2(tmem, ad + 4, bd0 + 4, IDESC, 1u);
                mma_tf32_ss_cg2(tmem, ad + 6, bd0 + 6, IDESC, 1u);
                MBARRIER_WAIT_PARITY(sb + SM_BUFF1, bufph);   // half1 cols free
                TCGEN05_FENCE_AFTER();
                mma_tf32_ss_cg2(tmem + MMA_N, ad + 0, bd1 + 0, IDESC, 0u);
                mma_tf32_ss_cg2(tmem + MMA_N, ad + 2, bd1 + 2, IDESC, 1u);
                mma_tf32_ss_cg2(tmem + MMA_N, ad + 4, bd1 + 4, IDESC, 1u);
                mma_tf32_ss_cg2(tmem + MMA_N, ad + 6, bd1 + 6, IDESC, 1u);
                TCGEN05_COMMIT_MC_CG2(sb + SM_MMAD + 8 * st, 0x3);
                if (++st == STAGES) { st = 0; ph ^= 1; }
            }
            bufph ^= 1;

            // ---- kc = 1..63: branch-free interleaved hot loop (R10 mainloop) ----
            for (int kc = 1; kc < KCHUNKS; kc++) {
                MBARRIER_WAIT_PARITY_RELAXED(sb + SM_FULL + 8 * st, ph);
                uint64_t ad = adesc[st], bd0 = bdesc0[st], bd1 = bdesc1[st];
                mma_tf32_ss_cg2(tmem,         ad + 0, bd0 + 0, IDESC, 1u);
                mma_tf32_ss_cg2(tmem + MMA_N, ad + 0, bd1 + 0, IDESC, 1u);
                mma_tf32_ss_cg2(tmem,         ad + 2, bd0 + 2, IDESC, 1u);
                mma_tf32_ss_cg2(tmem + MMA_N, ad + 2, bd1 + 2, IDESC, 1u);
                mma_tf32_ss_cg2(tmem,         ad + 4, bd0 + 4, IDESC, 1u);
                mma_tf32_ss_cg2(tmem + MMA_N, ad + 4, bd1 + 4, IDESC, 1u);
                mma_tf32_ss_cg2(tmem,         ad + 6, bd0 + 6, IDESC, 1u);
                mma_tf32_ss_cg2(tmem + MMA_N, ad + 6, bd1 + 6, IDESC, 1u);
                // stage consumed -> free in BOTH CTAs
                TCGEN05_COMMIT_MC_CG2(sb + SM_MMAD + 8 * st, 0x3);
                if (++st == STAGES) { st = 0; ph ^= 1; }
            }
            // accumulator ready -> epilogues in BOTH CTAs
            TCGEN05_COMMIT_MC_CG2(sb + SM_TILED, 0x3);
        }
    }

    // ================= Epilogue: warps 0-3, BOTH ranks =================
    // Each CTA's TMEM holds its own 128 rows of the M=256 x N=512 accumulator.
    // Release half0 (BUFF0) as soon as its 8 chunks are read so the next tile's
    // MMA can begin while half1 is still draining.
    if (wid < 4) {
        int ws = 0, wph = 0;  // work-ring consumer cursor
        int tph = 0;
        for (;;) {
            int t;
            MBARRIER_WAIT_PARITY_ACQC(sb + SM_WORKV + 8 * ws, wph);
            asm volatile("ld.shared.b32 %0, [%1];" : "=r"(t) : "r"(sb + SM_RING + 4 * ws));
            if (lane == 0) {
                if (rank == 0) { MBARRIER_ARRIVE(sb + SM_WORKF + 8 * ws); }
                else           { MBARRIER_ARRIVE_RANK0(sb + SM_WORKF + 8 * ws); }
            }
            if (++ws == WSLOTS) { ws = 0; wph ^= 1; }
            if (t < 0) break;

            int m_base, m_end, expert, n_base;
            decode_ptile(S, t, m_base, m_end, expert, n_base);
            MBARRIER_WAIT_PARITY(sb + SM_TILED, tph);
            tph ^= 1;
            TCGEN05_FENCE_AFTER();

            int row = m_base + (int)rank * BM + wid * 32 + lane;
            bool valid = (row < m_end);
            float* orow = out + (size_t)row * N_ + n_base;

            // 2-deep LDTM software pipeline: issue chunk c+1 before storing chunk c.
            uint32_t ra[32], rb[32];
            TCGEN05_LD_32X32B_X32(ra, tmem + 0 * 32);
            #pragma unroll
            for (int c = 0; c < BN / 32; c++) {
                TCGEN05_WAIT_LD();                     // completes the chunk issued for c
                uint32_t* cur = (c & 1) ? rb : ra;
                uint32_t* nxt = (c & 1) ? ra : rb;
                if (c < BN / 32 - 1) TCGEN05_LD_32X32B_X32(nxt, tmem + (c + 1) * 32);
                if (c == 8) {
                    // chunks 0-7 (half0 cols) fully read -> free half0 for next tile
                    TCGEN05_FENCE_BEFORE();
                    if (lane == 0) MBARRIER_ARRIVE_RANK0(sb + SM_BUFF0);
                }
                if (valid) {
                    float4* dst = (float4*)(orow + c * 32);
                    #pragma unroll
                    for (int j = 0; j < 8; j++) {
                        float4 v;
                        v.x = __uint_as_float(cur[4 * j + 0]);
                        v.y = __uint_as_float(cur[4 * j + 1]);
                        v.z = __uint_as_float(cur[4 * j + 2]);
                        v.w = __uint_as_float(cur[4 * j + 3]);
                        dst[j] = v;
                    }
                }
            }
            TCGEN05_FENCE_BEFORE();
            if (lane == 0) MBARRIER_ARRIVE_RANK0(sb + SM_BUFF1);
        }
    }

    __syncthreads();
    // no CTA may exit while peer traffic (cg2 TMA / commits / ring stores) is in flight
    CLUSTER_SYNC();
    if (wid == 4) {
        TCGEN05_DEALLOC_CG2(tmem, TMEM_COLS);
    }
    CLUSTER_SYNC();
#else
    // ---------- SIMT fallback (only runs if no sm_103a SASS exists) ----------
    Sched S;
    build_sched(segp, widxp, S);
    const int tid = threadIdx.x;
    int total_work = T_ * (N_ / 4);
    for (int w = blockIdx.x * blockDim.x + tid; w < total_work; w += gridDim.x * blockDim.x) {
        int rowi = w / (N_ / 4);
        int n4   = (w - rowi * (N_ / 4)) * 4;
        int seg = 0;
        #pragma unroll
        for (int i = 1; i < E_; i++)
            if (rowi >= S.p[i]) seg = i;
        int expert = S.widx[seg];
        const float4* arow = (const float4*)(a_raw + (size_t)rowi * K_);
        const float4* b0 = (const float4*)(b_raw + ((size_t)expert * N_ + n4 + 0) * K_);
        const float4* b1 = (const float4*)(b_raw + ((size_t)expert * N_ + n4 + 1) * K_);
        const float4* b2 = (const float4*)(b_raw + ((size_t)expert * N_ + n4 + 2) * K_);
        const float4* b3 = (const float4*)(b_raw + ((size_t)expert * N_ + n4 + 3) * K_);
        float s0 = 0.f, s1 = 0.f, s2 = 0.f, s3 = 0.f;
        for (int k = 0; k < K_ / 4; k++) {
            float4 av = __ldg(arow + k);
            float4 v0 = __ldg(b0 + k), v1 = __ldg(b1 + k), v2 = __ldg(b2 + k), v3 = __ldg(b3 + k);
            s0 += av.x * v0.x + av.y * v0.y + av.z * v0.z + av.w * v0.w;
            s1 += av.x * v1.x + av.y * v1.y + av.z * v1.z + av.w * v1.w;
            s2 += av.x * v2.x + av.y * v2.y + av.z * v2.z + av.w * v2.w;
            s3 += av.x * v3.x + av.y * v3.y + av.z * v3.z + av.w * v3.w;
        }
        float4 o; o.x = s0; o.y = s1; o.z = s2; o.w = s3;
        *(float4*)(out + (size_t)rowi * N_ + n4) = o;
    }
#endif
}

// ---------------- host launch ----------------
typedef CUresult (*cuTensorMapEncodeTiled_t)(
    CUtensorMap*, CUtensorMapDataType, cuuint32_t, void*,
    const cuuint64_t*, const cuuint64_t*, const cuuint32_t*, const cuuint32_t*,
    CUtensorMapInterleave, CUtensorMapSwizzle, CUtensorMapL2promotion, CUtensorMapFloatOOBfill);

extern "C" void kernel_launch(void* const* d_in, const int* in_sizes, int n_in,
                              void* d_out, int out_size) {
    const float* a = (const float*)d_in[0];
    const float* b = (const float*)d_in[1];
    // d_in[2] = preallocated c buffer (unused; result goes to d_out)
    // d_in[3] = batch_size, d_in[4] = weight_column_major (constants for this problem)
    const void* segp  = d_in[5];
    const void* widxp = d_in[6];

    // Resolve driver-API tensormap encoder through the runtime (no -lcuda needed).
    void* fp = nullptr;
    cudaDriverEntryPointQueryResult qres;
    cudaGetDriverEntryPoint("cuTensorMapEncodeTiled", &fp, cudaEnableDefault, &qres);
    if (!fp) return;
    cuTensorMapEncodeTiled_t encode = (cuTensorMapEncodeTiled_t)fp;

    CUtensorMap tma_a, tma_b;
    {
        cuuint64_t dims[2]    = {(cuuint64_t)K_, (cuuint64_t)T_};
        cuuint64_t strides[1] = {(cuuint64_t)K_ * sizeof(float)};
        cuuint32_t box[2]     = {BK, HBOX};
        cuuint32_t es[2]      = {1, 1};
        encode(&tma_a, CU_TENSOR_MAP_DATA_TYPE_FLOAT32, 2, (void*)a,
               dims, strides, box, es,
               CU_TENSOR_MAP_INTERLEAVE_NONE, CU_TENSOR_MAP_SWIZZLE_128B,
               CU_TENSOR_MAP_L2_PROMOTION_L2_128B, CU_TENSOR_MAP_FLOAT_OOB_FILL_NONE);
    }
    {
        cuuint64_t dims[3]    = {(cuuint64_t)K_, (cuuint64_t)N_, (cuuint64_t)E_};
        cuuint64_t strides[2] = {(cuuint64_t)K_ * sizeof(float),
                                 (cuuint64_t)N_ * (cuuint64_t)K_ * sizeof(float)};
        cuuint32_t box[3]     = {BK, HBOX, 1};
        cuuint32_t es[3]      = {1, 1, 1};
        encode(&tma_b, CU_TENSOR_MAP_DATA_TYPE_FLOAT32, 3, (void*)b,
               dims, strides, box, es,
               CU_TENSOR_MAP_INTERLEAVE_NONE, CU_TENSOR_MAP_SWIZZLE_128B,
               CU_TENSOR_MAP_L2_PROMOTION_L2_128B, CU_TENSOR_MAP_FLOAT_OOB_FILL_NONE);
    }

    cudaFuncSetAttribute(gg_tf32_kernel, cudaFuncAttributeMaxDynamicSharedMemorySize, SMEM_TOTAL);

    int dev = 0, sms = 148;
    cudaGetDevice(&dev);
    cudaDeviceGetAttribute(&sms, cudaDevAttrMultiProcessorCount, dev);

    int grid = OCC * sms;       // one CTA per SM
    grid &= ~(CLUSTER - 1);     // grid must be a multiple of the cluster size

    gg_init_kernel<<<1, 1>>>();  // reset the dynamic-scheduler ticket (every replay)
    gg_tf32_kernel<<<grid, NTHREADS, SMEM_TOTAL>>>(tma_a, tma_b, a, b, segp, widxp, (float*)d_out);
}